// round 6
// baseline (speedup 1.0000x reference)
#include <cuda_runtime.h>
#include <cuda_bf16.h>

// Problem constants (fixed by the reference)
#define B_      8
#define N_      4096
#define C_      128
#define K_      16
#define NPOINT_ 1024   // N/4

// Scratch: transposed feature map fmT[(b*N + n)*C + c] = feature_map[b, c, n]
__device__ float g_fmT[B_ * N_ * C_];          // 16 MB
__device__ int   g_cents[B_ * NPOINT_];        // FPS centroid indices

// ---------------------------------------------------------------------------
// Kernel A: transpose feature_map (B,C,N) -> fmT (B*N, C)
// grid (N/32, C/32, B), block (32, 8), 32x32 tiles
// ---------------------------------------------------------------------------
__global__ void transpose_kernel(const float* __restrict__ fm) {
    __shared__ float tile[32][33];
    const int b  = blockIdx.z;
    const int n0 = blockIdx.x * 32;
    const int c0 = blockIdx.y * 32;
    const int tx = threadIdx.x, ty = threadIdx.y;

    const float* src = fm + (long)b * C_ * N_;
#pragma unroll
    for (int j = 0; j < 4; ++j) {
        int c = c0 + ty + 8 * j;
        tile[ty + 8 * j][tx] = src[(long)c * N_ + (n0 + tx)];
    }
    __syncthreads();
    float* dst = g_fmT + (long)b * N_ * C_;
#pragma unroll
    for (int j = 0; j < 4; ++j) {
        int n = n0 + ty + 8 * j;
        dst[(long)n * C_ + (c0 + tx)] = tile[tx][ty + 8 * j];
    }
}

// ---------------------------------------------------------------------------
// Kernel B: farthest point sampling. One block per batch, 1024 threads,
// 4 points per thread, everything in registers. The argmax reduction carries
// (value, index, x, y, z) so the winner publishes the next centroid's coords
// directly — no 48KB xyz mirror, only ~700B of static shared.
// Also writes vertices_pool (first B*3*NPOINT floats of d_out).
// ---------------------------------------------------------------------------
__global__ __launch_bounds__(1024, 1)
void fps_kernel(const float* __restrict__ vert, float* __restrict__ vpool) {
    __shared__ unsigned s_wval[32];
    __shared__ int      s_widx[32];
    __shared__ float    s_wx[32], s_wy[32], s_wz[32];
    __shared__ float    s_cx, s_cy, s_cz;

    const int b    = blockIdx.x;
    const int tid  = threadIdx.x;
    const int lane = tid & 31;
    const int warp = tid >> 5;
    const int T    = 1024;

    const float* vb = vert + (long)b * 3 * N_;

    float xr[4], yr[4], zr[4], d[4];
#pragma unroll
    for (int p = 0; p < 4; ++p) {
        int n = tid + p * T;
        xr[p] = vb[n];
        yr[p] = vb[N_ + n];
        zr[p] = vb[2 * N_ + n];
        d[p]  = 1e10f;
    }

    // Seed: centroid 0 is point 0 (owned by tid 0, p=0). Matches reference scan.
    if (tid == 0) {
        s_cx = xr[0]; s_cy = yr[0]; s_cz = zr[0];
        g_cents[b * NPOINT_] = 0;
        vpool[((long)b * 3 + 0) * NPOINT_] = xr[0];
        vpool[((long)b * 3 + 1) * NPOINT_] = yr[0];
        vpool[((long)b * 3 + 2) * NPOINT_] = zr[0];
    }
    __syncthreads();

    for (int it = 1; it < NPOINT_; ++it) {
        const float cx = s_cx, cy = s_cy, cz = s_cz;

        float bestv = -1.0f;
        int   bestn = 0;
        float bx = 0.f, by = 0.f, bz = 0.f;
#pragma unroll
        for (int p = 0; p < 4; ++p) {
            float dx = xr[p] - cx;
            float dy = yr[p] - cy;
            float dz = zr[p] - cz;
            // exact association, no FMA contraction: (dx^2 + dy^2) + dz^2
            float dist = __fadd_rn(__fadd_rn(__fmul_rn(dx, dx), __fmul_rn(dy, dy)),
                                   __fmul_rn(dz, dz));
            float nd = fminf(d[p], dist);
            d[p] = nd;
            if (nd > bestv) {
                bestv = nd; bestn = tid + p * T;
                bx = xr[p]; by = yr[p]; bz = zr[p];
            }
        }

        // warp argmax: (max value, min index among ties) = first-occurrence order
        unsigned bv   = __float_as_uint(bestv);          // bestv >= 0 -> monotonic bits
        unsigned wmax = __reduce_max_sync(0xffffffffu, bv);
        int cand = (bv == wmax) ? bestn : 0x7fffffff;
        int wmin = __reduce_min_sync(0xffffffffu, cand);
        if (bv == wmax && bestn == wmin) {               // unique lane (indices unique)
            s_wval[warp] = wmax; s_widx[warp] = wmin;
            s_wx[warp] = bx; s_wy[warp] = by; s_wz[warp] = bz;
        }
        __syncthreads();

        if (warp == 0) {
            unsigned v  = s_wval[lane];
            int      ix = s_widx[lane];
            float    fx = s_wx[lane], fy = s_wy[lane], fz = s_wz[lane];
            unsigned m  = __reduce_max_sync(0xffffffffu, v);
            int c2 = (v == m) ? ix : 0x7fffffff;
            int g  = __reduce_min_sync(0xffffffffu, c2);
            if (v == m && ix == g) {                     // unique winning lane
                s_cx = fx; s_cy = fy; s_cz = fz;
                g_cents[b * NPOINT_ + it] = g;
                vpool[((long)b * 3 + 0) * NPOINT_ + it] = fx;
                vpool[((long)b * 3 + 1) * NPOINT_ + it] = fy;
                vpool[((long)b * 3 + 2) * NPOINT_ + it] = fz;
            }
        }
        __syncthreads();
    }
}

// ---------------------------------------------------------------------------
// Kernel C: gather K neighbors of each sampled point from fmT, max-pool over K,
// write feature_map_pool (B,C,NPOINT). One block per sampled point, c = tid.
// idx dtype (int32 vs int64) detected from data: int64 high words are all 0.
// ---------------------------------------------------------------------------
__global__ void gather_max_kernel(const void* __restrict__ idxp,
                                  float* __restrict__ fpool) {
    const int bp = blockIdx.x;            // 0 .. B*NPOINT-1
    const int b  = bp >> 10;              // / NPOINT_
    const int i  = bp & (NPOINT_ - 1);
    const int c  = threadIdx.x;

    const int s = g_cents[bp];

    const int* i32 = (const int*)idxp;
    const bool is64 = ((i32[1] | i32[3] | i32[5]) == 0);

    const long base = ((long)(b * N_ + s)) * K_;
    const long long* i64 = (const long long*)idxp;

    float m = -3.4028235e38f;
#pragma unroll
    for (int k = 0; k < K_; ++k) {
        long g = is64 ? (long)i64[base + k] : (long)i32[base + k];
        m = fmaxf(m, g_fmT[g * C_ + c]);
    }
    fpool[((long)b * C_ + c) * NPOINT_ + i] = m;
}

// ---------------------------------------------------------------------------
extern "C" void kernel_launch(void* const* d_in, const int* in_sizes, int n_in,
                              void* d_out, int out_size) {
    const float* vert = (const float*)d_in[0];   // (B,3,N)   float32
    const float* fm   = (const float*)d_in[1];   // (B,C,N)   float32
    const void*  idx  = d_in[2];                 // (B*N*K,)  int64 or int32

    float* out   = (float*)d_out;
    float* vpool = out;                          // (B,3,NPOINT)
    float* fpool = out + (long)B_ * 3 * NPOINT_; // (B,C,NPOINT)

    transpose_kernel<<<dim3(N_ / 32, C_ / 32, B_), dim3(32, 8)>>>(fm);
    fps_kernel<<<B_, 1024>>>(vert, vpool);
    gather_max_kernel<<<B_ * NPOINT_, C_>>>(idx, fpool);
}

// round 9
// speedup vs baseline: 1.2182x; 1.2182x over previous
#include <cuda_runtime.h>
#include <cuda_bf16.h>

// Problem constants (fixed by the reference)
#define B_      8
#define N_      4096
#define C_      128
#define K_      16
#define NPOINT_ 1024   // N/4

// Scratch: transposed feature map fmT[(b*N + n)*C + c] = feature_map[b, c, n]
__device__ float g_fmT[B_ * N_ * C_];          // 16 MB
__device__ int   g_cents[B_ * NPOINT_];        // FPS centroid indices

// ---------------------------------------------------------------------------
// Packed f32x2 helpers (sm_103a). Per-lane .rn rounding == scalar __fadd_rn /
// __fmul_rn, so results are bit-exact vs the scalar version.
// ---------------------------------------------------------------------------
__device__ __forceinline__ unsigned long long pack2(float lo, float hi) {
    unsigned long long r;
    asm("mov.b64 %0, {%1, %2};" : "=l"(r) : "f"(lo), "f"(hi));
    return r;
}
__device__ __forceinline__ void unpack2(unsigned long long v, float& lo, float& hi) {
    asm("mov.b64 {%0, %1}, %2;" : "=f"(lo), "=f"(hi) : "l"(v));
}
__device__ __forceinline__ unsigned long long add2(unsigned long long a,
                                                   unsigned long long b) {
    unsigned long long r;
    asm("add.rn.f32x2 %0, %1, %2;" : "=l"(r) : "l"(a), "l"(b));
    return r;
}
__device__ __forceinline__ unsigned long long mul2(unsigned long long a,
                                                   unsigned long long b) {
    unsigned long long r;
    asm("mul.rn.f32x2 %0, %1, %2;" : "=l"(r) : "l"(a), "l"(b));
    return r;
}
__device__ __forceinline__ float fneg_exact(float x) {   // sign-bit XOR, alu pipe
    return __uint_as_float(__float_as_uint(x) ^ 0x80000000u);
}

// ---------------------------------------------------------------------------
// Kernel A: transpose feature_map (B,C,N) -> fmT (B*N, C)
// ---------------------------------------------------------------------------
__global__ void transpose_kernel(const float* __restrict__ fm) {
    __shared__ float tile[32][33];
    const int b  = blockIdx.z;
    const int n0 = blockIdx.x * 32;
    const int c0 = blockIdx.y * 32;
    const int tx = threadIdx.x, ty = threadIdx.y;

    const float* src = fm + (long)b * C_ * N_;
#pragma unroll
    for (int j = 0; j < 4; ++j) {
        int c = c0 + ty + 8 * j;
        tile[ty + 8 * j][tx] = src[(long)c * N_ + (n0 + tx)];
    }
    __syncthreads();
    float* dst = g_fmT + (long)b * N_ * C_;
#pragma unroll
    for (int j = 0; j < 4; ++j) {
        int n = n0 + ty + 8 * j;
        dst[(long)n * C_ + (c0 + tx)] = tile[tx][ty + 8 * j];
    }
}

// ---------------------------------------------------------------------------
// Kernel B: farthest point sampling. One block per batch, 1024 threads,
// 4 consecutive points per thread (n = tid*4 + p). Packed f32x2 distance math,
// single barrier per iteration (ping-pong shared + redundant 2nd-level reduce
// in every warp), ballot+ffs tie-breaking (== first-occurrence argmax).
// ---------------------------------------------------------------------------
__global__ __launch_bounds__(1024, 1)
void fps_kernel(const float* __restrict__ vert, float* __restrict__ vpool) {
    __shared__ unsigned s_val[2][32];
    __shared__ int      s_n[2][32];     // reserved (winner writes gmem directly)
    __shared__ float    s_x[2][32], s_y[2][32], s_z[2][32];

    const int b    = blockIdx.x;
    const int tid  = threadIdx.x;
    const int lane = tid & 31;
    const int warp = tid >> 5;

    const float* vb = vert + (long)b * 3 * N_;

    // coalesced float4 loads: thread owns points 4*tid .. 4*tid+3
    const float4 xv = *(const float4*)(vb + 4 * tid);
    const float4 yv = *(const float4*)(vb + N_ + 4 * tid);
    const float4 zv = *(const float4*)(vb + 2 * N_ + 4 * tid);

    const unsigned long long x01 = pack2(xv.x, xv.y), x23 = pack2(xv.z, xv.w);
    const unsigned long long y01 = pack2(yv.x, yv.y), y23 = pack2(yv.z, yv.w);
    const unsigned long long z01 = pack2(zv.x, zv.y), z23 = pack2(zv.z, zv.w);

    float d0 = 1e10f, d1 = 1e10f, d2 = 1e10f, d3 = 1e10f;

    // Seed: centroid 0 is point 0 (thread 0, p=0). Matches reference scan.
    if (tid == 0) {
        s_x[0][0] = xv.x; s_y[0][0] = yv.x; s_z[0][0] = zv.x;
        g_cents[b * NPOINT_] = 0;
        vpool[((long)b * 3 + 0) * NPOINT_] = xv.x;
        vpool[((long)b * 3 + 1) * NPOINT_] = yv.x;
        vpool[((long)b * 3 + 2) * NPOINT_] = zv.x;
    }
    __syncthreads();
    float cx = s_x[0][0], cy = s_y[0][0], cz = s_z[0][0];

    for (int it = 1; it < NPOINT_; ++it) {
        const int P = it & 1;

        // packed (-c, -c) per dimension (exact negation via sign flip)
        const float ncx = fneg_exact(cx), ncy = fneg_exact(cy), ncz = fneg_exact(cz);
        const unsigned long long nx = pack2(ncx, ncx);
        const unsigned long long ny = pack2(ncy, ncy);
        const unsigned long long nz = pack2(ncz, ncz);

        // dist = (dx*dx + dy*dy) + dz*dz, two points per packed op
        unsigned long long dx01 = add2(x01, nx), dx23 = add2(x23, nx);
        unsigned long long dy01 = add2(y01, ny), dy23 = add2(y23, ny);
        unsigned long long dz01 = add2(z01, nz), dz23 = add2(z23, nz);
        unsigned long long s01 = add2(add2(mul2(dx01, dx01), mul2(dy01, dy01)),
                                      mul2(dz01, dz01));
        unsigned long long s23 = add2(add2(mul2(dx23, dx23), mul2(dy23, dy23)),
                                      mul2(dz23, dz23));
        float q0, q1, q2, q3;
        unpack2(s01, q0, q1);
        unpack2(s23, q2, q3);

        d0 = fminf(d0, q0); d1 = fminf(d1, q1);
        d2 = fminf(d2, q2); d3 = fminf(d3, q3);

        const float bestv = fmaxf(fmaxf(d0, d1), fmaxf(d2, d3));

        // warp argmax with first-occurrence ties: indices are ordered by
        // (lane, p), so min lane via ballot+ffs, min p via ordered scan below.
        const unsigned bv    = __float_as_uint(bestv);   // bestv >= 0 -> monotonic
        const unsigned wmax  = __reduce_max_sync(0xffffffffu, bv);
        const unsigned mask  = __ballot_sync(0xffffffffu, bv == wmax);
        const int      wlane = __ffs(mask) - 1;

        int   myn = 0;
        float px = 0.f, py = 0.f, pz = 0.f;
        if (lane == wlane) {
            int p;
            if      (d0 == bestv) { p = 0; px = xv.x; py = yv.x; pz = zv.x; }
            else if (d1 == bestv) { p = 1; px = xv.y; py = yv.y; pz = zv.y; }
            else if (d2 == bestv) { p = 2; px = xv.z; py = yv.z; pz = zv.z; }
            else                  { p = 3; px = xv.w; py = yv.w; pz = zv.w; }
            myn = (tid << 2) | p;
            s_val[P][warp] = wmax;
            s_x[P][warp] = px; s_y[P][warp] = py; s_z[P][warp] = pz;
        }
        __syncthreads();   // the ONLY barrier per iteration (ping-pong buffers)

        // second level, done redundantly by every warp (no broadcast needed)
        const unsigned sv    = s_val[P][lane];
        const unsigned m2    = __reduce_max_sync(0xffffffffu, sv);
        const unsigned mask2 = __ballot_sync(0xffffffffu, sv == m2);
        const int      wwin  = __ffs(mask2) - 1;

        cx = s_x[P][wwin]; cy = s_y[P][wwin]; cz = s_z[P][wwin];

        if (warp == wwin && lane == wlane) {   // unique global winner
            g_cents[b * NPOINT_ + it] = myn;
            vpool[((long)b * 3 + 0) * NPOINT_ + it] = px;
            vpool[((long)b * 3 + 1) * NPOINT_ + it] = py;
            vpool[((long)b * 3 + 2) * NPOINT_ + it] = pz;
        }
    }
    (void)s_n;
}

// ---------------------------------------------------------------------------
// Kernel C: gather K neighbors of each sampled point from fmT, max-pool over K,
// write feature_map_pool (B,C,NPOINT). One block per sampled point, c = tid.
// idx dtype (int32 vs int64) detected from data: int64 high words are all 0.
// ---------------------------------------------------------------------------
__global__ void gather_max_kernel(const void* __restrict__ idxp,
                                  float* __restrict__ fpool) {
    const int bp = blockIdx.x;            // 0 .. B*NPOINT-1
    const int b  = bp >> 10;              // / NPOINT_
    const int i  = bp & (NPOINT_ - 1);
    const int c  = threadIdx.x;

    const int s = g_cents[bp];

    const int* i32 = (const int*)idxp;
    const bool is64 = ((i32[1] | i32[3] | i32[5]) == 0);

    const long base = ((long)(b * N_ + s)) * K_;
    const long long* i64 = (const long long*)idxp;

    float m = -3.4028235e38f;
#pragma unroll
    for (int k = 0; k < K_; ++k) {
        long g = is64 ? (long)i64[base + k] : (long)i32[base + k];
        m = fmaxf(m, g_fmT[g * C_ + c]);
    }
    fpool[((long)b * C_ + c) * NPOINT_ + i] = m;
}

// ---------------------------------------------------------------------------
extern "C" void kernel_launch(void* const* d_in, const int* in_sizes, int n_in,
                              void* d_out, int out_size) {
    const float* vert = (const float*)d_in[0];   // (B,3,N)   float32
    const float* fm   = (const float*)d_in[1];   // (B,C,N)   float32
    const void*  idx  = d_in[2];                 // (B*N*K,)  int64 or int32

    float* out   = (float*)d_out;
    float* vpool = out;                          // (B,3,NPOINT)
    float* fpool = out + (long)B_ * 3 * NPOINT_; // (B,C,NPOINT)

    transpose_kernel<<<dim3(N_ / 32, C_ / 32, B_), dim3(32, 8)>>>(fm);
    fps_kernel<<<B_, 1024>>>(vert, vpool);
    gather_max_kernel<<<B_ * NPOINT_, C_>>>(idx, fpool);
}

// round 11
// speedup vs baseline: 1.3072x; 1.0731x over previous
#include <cuda_runtime.h>
#include <cuda_bf16.h>

// Problem constants (fixed by the reference)
#define B_      8
#define N_      4096
#define C_      128
#define K_      16
#define NPOINT_ 1024   // N/4

typedef unsigned long long ull;

// Scratch: transposed feature map fmT[(b*N + n)*C + c] = feature_map[b, c, n]
__device__ float g_fmT[B_ * N_ * C_];          // 16 MB
__device__ int   g_cents[B_ * NPOINT_];        // FPS centroid indices

// ---------------------------------------------------------------------------
// Packed f32x2 helpers (sm_103a). Per-lane .rn rounding == scalar __fadd_rn /
// __fsub_rn / __fmul_rn, so results are bit-exact vs the scalar version.
// ---------------------------------------------------------------------------
__device__ __forceinline__ ull pack2(float lo, float hi) {
    ull r;
    asm("mov.b64 %0, {%1, %2};" : "=l"(r) : "f"(lo), "f"(hi));
    return r;
}
__device__ __forceinline__ void unpack2(ull v, float& lo, float& hi) {
    asm("mov.b64 {%0, %1}, %2;" : "=f"(lo), "=f"(hi) : "l"(v));
}
__device__ __forceinline__ ull add2(ull a, ull b) {
    ull r;
    asm("add.rn.f32x2 %0, %1, %2;" : "=l"(r) : "l"(a), "l"(b));
    return r;
}
__device__ __forceinline__ ull sub2(ull a, ull b) {
    ull r;
    asm("sub.rn.f32x2 %0, %1, %2;" : "=l"(r) : "l"(a), "l"(b));
    return r;
}
__device__ __forceinline__ ull mul2(ull a, ull b) {
    ull r;
    asm("mul.rn.f32x2 %0, %1, %2;" : "=l"(r) : "l"(a), "l"(b));
    return r;
}

// ---------------------------------------------------------------------------
// Kernel A: transpose feature_map (B,C,N) -> fmT (B*N, C)
// ---------------------------------------------------------------------------
__global__ void transpose_kernel(const float* __restrict__ fm) {
    __shared__ float tile[32][33];
    const int b  = blockIdx.z;
    const int n0 = blockIdx.x * 32;
    const int c0 = blockIdx.y * 32;
    const int tx = threadIdx.x, ty = threadIdx.y;

    const float* src = fm + (long)b * C_ * N_;
#pragma unroll
    for (int j = 0; j < 4; ++j) {
        int c = c0 + ty + 8 * j;
        tile[ty + 8 * j][tx] = src[(long)c * N_ + (n0 + tx)];
    }
    __syncthreads();
    float* dst = g_fmT + (long)b * N_ * C_;
#pragma unroll
    for (int j = 0; j < 4; ++j) {
        int n = n0 + ty + 8 * j;
        dst[(long)n * C_ + (c0 + tx)] = tile[tx][ty + 8 * j];
    }
}

// ---------------------------------------------------------------------------
// Kernel B: farthest point sampling. One block per batch, 512 threads
// (16 warps), 8 consecutive points per thread (n = tid*8 + p). Packed f32x2
// distance math with sub.rn.f32x2, one barrier per iteration (ping-pong
// shared, redundant 2nd-level reduce in every warp), ballot+ffs tie-breaking
// (== first-occurrence argmax; indices ordered by (warp, lane, p)).
// ---------------------------------------------------------------------------
__global__ __launch_bounds__(512, 1)
void fps_kernel(const float* __restrict__ vert, float* __restrict__ vpool) {
    __shared__ unsigned s_val[2][32];
    __shared__ float4   s_rec[2][32];    // (x, y, z, unused) of per-warp winner

    const int b    = blockIdx.x;
    const int tid  = threadIdx.x;
    const int lane = tid & 31;
    const int warp = tid >> 5;

    const float* vb = vert + (long)b * 3 * N_;

    // coalesced float4 loads: thread owns points 8*tid .. 8*tid+7
    const float4 xa = *(const float4*)(vb + 8 * tid);
    const float4 xc = *(const float4*)(vb + 8 * tid + 4);
    const float4 ya = *(const float4*)(vb + N_ + 8 * tid);
    const float4 yc = *(const float4*)(vb + N_ + 8 * tid + 4);
    const float4 za = *(const float4*)(vb + 2 * N_ + 8 * tid);
    const float4 zc = *(const float4*)(vb + 2 * N_ + 8 * tid + 4);

    const ull x01 = pack2(xa.x, xa.y), x23 = pack2(xa.z, xa.w);
    const ull x45 = pack2(xc.x, xc.y), x67 = pack2(xc.z, xc.w);
    const ull y01 = pack2(ya.x, ya.y), y23 = pack2(ya.z, ya.w);
    const ull y45 = pack2(yc.x, yc.y), y67 = pack2(yc.z, yc.w);
    const ull z01 = pack2(za.x, za.y), z23 = pack2(za.z, za.w);
    const ull z45 = pack2(zc.x, zc.y), z67 = pack2(zc.z, zc.w);

    float d0 = 1e10f, d1 = 1e10f, d2 = 1e10f, d3 = 1e10f;
    float d4 = 1e10f, d5 = 1e10f, d6 = 1e10f, d7 = 1e10f;

    // zero unused reduction slots (warps 16..31 don't exist; values >= 0 win)
    if (tid < 64) s_val[tid >> 5][tid & 31] = 0u;

    // Seed: centroid 0 is point 0 — all threads read it straight from gmem
    // (L1/L2 broadcast, one time). Matches the reference scan start.
    float cx = __ldg(vb);
    float cy = __ldg(vb + N_);
    float cz = __ldg(vb + 2 * N_);
    if (tid == 0) {
        g_cents[b * NPOINT_] = 0;
        vpool[((long)b * 3 + 0) * NPOINT_] = cx;
        vpool[((long)b * 3 + 1) * NPOINT_] = cy;
        vpool[((long)b * 3 + 2) * NPOINT_] = cz;
    }
    __syncthreads();   // covers the s_val zero-init

    // winner-lane state persists across the barrier in registers
    float px = 0.f, py = 0.f, pz = 0.f;
    int   myn = 0;

    for (int it = 1; it < NPOINT_; ++it) {
        const int P = it & 1;

        const ull c2x = pack2(cx, cx);
        const ull c2y = pack2(cy, cy);
        const ull c2z = pack2(cz, cz);

        // dist = (dx*dx + dy*dy) + dz*dz, two points per packed op, exact rn
        ull t, s;
        float q0, q1;

        t = sub2(x01, c2x); s = mul2(t, t);
        t = sub2(y01, c2y); s = add2(s, mul2(t, t));
        t = sub2(z01, c2z); s = add2(s, mul2(t, t));
        unpack2(s, q0, q1); d0 = fminf(d0, q0); d1 = fminf(d1, q1);

        t = sub2(x23, c2x); s = mul2(t, t);
        t = sub2(y23, c2y); s = add2(s, mul2(t, t));
        t = sub2(z23, c2z); s = add2(s, mul2(t, t));
        unpack2(s, q0, q1); d2 = fminf(d2, q0); d3 = fminf(d3, q1);

        t = sub2(x45, c2x); s = mul2(t, t);
        t = sub2(y45, c2y); s = add2(s, mul2(t, t));
        t = sub2(z45, c2z); s = add2(s, mul2(t, t));
        unpack2(s, q0, q1); d4 = fminf(d4, q0); d5 = fminf(d5, q1);

        t = sub2(x67, c2x); s = mul2(t, t);
        t = sub2(y67, c2y); s = add2(s, mul2(t, t));
        t = sub2(z67, c2z); s = add2(s, mul2(t, t));
        unpack2(s, q0, q1); d6 = fminf(d6, q0); d7 = fminf(d7, q1);

        const float bestv = fmaxf(fmaxf(fmaxf(d0, d1), fmaxf(d2, d3)),
                                  fmaxf(fmaxf(d4, d5), fmaxf(d6, d7)));

        // warp argmax, first-occurrence ties: REDUX max + min lane via ballot
        const unsigned bv    = __float_as_uint(bestv);   // bestv >= 0 -> monotonic
        const unsigned wmax  = __reduce_max_sync(0xffffffffu, bv);
        const unsigned mask  = __ballot_sync(0xffffffffu, bv == wmax);
        const int      wlane = __ffs(mask) - 1;

        if (lane == wlane) {
            // branchless first-occurrence select over the 8 local candidates
            const bool e0 = (d0 == bestv), e1 = (d1 == bestv), e2 = (d2 == bestv);
            const bool e3 = (d3 == bestv), e4 = (d4 == bestv), e5 = (d5 == bestv);
            const bool e6 = (d6 == bestv);
            px  = e0 ? xa.x : e1 ? xa.y : e2 ? xa.z : e3 ? xa.w
                : e4 ? xc.x : e5 ? xc.y : e6 ? xc.z : xc.w;
            py  = e0 ? ya.x : e1 ? ya.y : e2 ? ya.z : e3 ? ya.w
                : e4 ? yc.x : e5 ? yc.y : e6 ? yc.z : yc.w;
            pz  = e0 ? za.x : e1 ? za.y : e2 ? za.z : e3 ? za.w
                : e4 ? zc.x : e5 ? zc.y : e6 ? zc.z : zc.w;
            const int p = e0 ? 0 : e1 ? 1 : e2 ? 2 : e3 ? 3
                        : e4 ? 4 : e5 ? 5 : e6 ? 6 : 7;
            myn = (tid << 3) | p;
            s_val[P][warp] = wmax;
            s_rec[P][warp] = make_float4(px, py, pz, 0.f);
        }
        __syncthreads();   // the ONLY barrier per iteration (ping-pong buffers)

        // second level, done redundantly by every warp (no broadcast barrier)
        const unsigned sv    = s_val[P][lane];
        const unsigned m2    = __reduce_max_sync(0xffffffffu, sv);
        const unsigned mask2 = __ballot_sync(0xffffffffu, sv == m2);
        const int      wwin  = __ffs(mask2) - 1;

        const float4 r = s_rec[P][wwin];   // LDS.128 broadcast
        cx = r.x; cy = r.y; cz = r.z;

        if (warp == wwin && lane == wlane) {   // unique global winner
            g_cents[b * NPOINT_ + it] = myn;
            vpool[((long)b * 3 + 0) * NPOINT_ + it] = px;
            vpool[((long)b * 3 + 1) * NPOINT_ + it] = py;
            vpool[((long)b * 3 + 2) * NPOINT_ + it] = pz;
        }
    }
}

// ---------------------------------------------------------------------------
// Kernel C: gather K neighbors of each sampled point from fmT, max-pool over K,
// write feature_map_pool (B,C,NPOINT). One block per sampled point, c = tid.
// idx dtype (int32 vs int64) detected from data: int64 high words are all 0.
// ---------------------------------------------------------------------------
__global__ void gather_max_kernel(const void* __restrict__ idxp,
                                  float* __restrict__ fpool) {
    const int bp = blockIdx.x;            // 0 .. B*NPOINT-1
    const int b  = bp >> 10;              // / NPOINT_
    const int i  = bp & (NPOINT_ - 1);
    const int c  = threadIdx.x;

    const int s = g_cents[bp];

    const int* i32 = (const int*)idxp;
    const bool is64 = ((i32[1] | i32[3] | i32[5]) == 0);

    const long base = ((long)(b * N_ + s)) * K_;
    const long long* i64 = (const long long*)idxp;

    float m = -3.4028235e38f;
#pragma unroll
    for (int k = 0; k < K_; ++k) {
        long g = is64 ? (long)i64[base + k] : (long)i32[base + k];
        m = fmaxf(m, g_fmT[g * C_ + c]);
    }
    fpool[((long)b * C_ + c) * NPOINT_ + i] = m;
}

// ---------------------------------------------------------------------------
extern "C" void kernel_launch(void* const* d_in, const int* in_sizes, int n_in,
                              void* d_out, int out_size) {
    const float* vert = (const float*)d_in[0];   // (B,3,N)   float32
    const float* fm   = (const float*)d_in[1];   // (B,C,N)   float32
    const void*  idx  = d_in[2];                 // (B*N*K,)  int64 or int32

    float* out   = (float*)d_out;
    float* vpool = out;                          // (B,3,NPOINT)
    float* fpool = out + (long)B_ * 3 * NPOINT_; // (B,C,NPOINT)

    transpose_kernel<<<dim3(N_ / 32, C_ / 32, B_), dim3(32, 8)>>>(fm);
    fps_kernel<<<B_, 512>>>(vert, vpool);
    gather_max_kernel<<<B_ * NPOINT_, C_>>>(idx, fpool);
}